// round 8
// baseline (speedup 1.0000x reference)
#include <cuda_runtime.h>
#include <cuda_bf16.h>
#include <math.h>
#include <stdint.h>

#define Bn 2
#define Sn 2048
#define Dn 1024
#define Hn 16
#define HDn 64
#define BSn (Bn*Sn)      // 4096
#define N3D (3*Dn)       // 3072
#define NQKV (Bn*Hn*Sn*HDn)

// GEMM slot (k32 stage): A 128 rows x 128B (16KB) | B 64 rows x 128B (8KB)
#define SLOT_G 24576
#define SMEM_G (2*SLOT_G)     // 49152 -> 3 CTAs/SM
// scores single-shot: Ah|Al|Bh|Bl regions of 16KB each
#define SMEM_SC 65536

// ---------------- bf16 hi/lo scratch (device globals) ----------------
__device__ __nv_bfloat16 s_hs_h[BSn*Dn],  s_hs_l[BSn*Dn];
__device__ __nv_bfloat16 s_wa_h[N3D*Dn],  s_wa_l[N3D*Dn];   // transposed [N][K]
__device__ __nv_bfloat16 s_wp_h[Dn*Dn],   s_wp_l[Dn*Dn];    // transposed [N][K]
__device__ __nv_bfloat16 g_q_h[NQKV], g_q_l[NQKV];          // [bh][s][hd]
__device__ __nv_bfloat16 g_k_h[NQKV], g_k_l[NQKV];          // [bh][s][hd]
__device__ __nv_bfloat16 g_v_h[NQKV], g_v_l[NQKV];          // [bh][hd][s] (transposed)
__device__ __nv_bfloat16 g_att_h[NQKV], g_att_l[NQKV];      // [bh][s][hd]
__device__ __nv_bfloat16 g_w_h[(size_t)Bn*Hn*Sn*Sn];
__device__ __nv_bfloat16 g_w_l[(size_t)Bn*Hn*Sn*Sn];

// ---------------- helpers ----------------
__device__ __forceinline__ uint32_t s2u(const void* p) {
    return (uint32_t)__cvta_generic_to_shared(p);
}
__device__ __forceinline__ void ldsm4(uint32_t& r0, uint32_t& r1, uint32_t& r2,
                                      uint32_t& r3, uint32_t a) {
    asm volatile("ldmatrix.sync.aligned.m8n8.x4.shared.b16 {%0,%1,%2,%3},[%4];"
                 : "=r"(r0), "=r"(r1), "=r"(r2), "=r"(r3) : "r"(a));
}
#define MMA(c, a, b) asm volatile( \
    "mma.sync.aligned.m16n8k16.row.col.f32.bf16.bf16.f32 " \
    "{%0,%1,%2,%3},{%4,%5,%6,%7},{%8,%9},{%0,%1,%2,%3};" \
    : "+f"((c)[0]), "+f"((c)[1]), "+f"((c)[2]), "+f"((c)[3]) \
    : "r"((a)[0]), "r"((a)[1]), "r"((a)[2]), "r"((a)[3]), "r"((b)[0]), "r"((b)[1]))

__device__ __forceinline__ void cpa16(uint32_t dst, const void* src) {
    asm volatile("cp.async.cg.shared.global [%0], [%1], 16;" :: "r"(dst), "l"(src));
}
#define CP_COMMIT() asm volatile("cp.async.commit_group;")
#define CP_WAIT0()  asm volatile("cp.async.wait_group 0;")

// byte offset of 16B chunk c (0..7) in swizzled 128B row
__device__ __forceinline__ uint32_t swz(int row, int c) {
    return (uint32_t)row * 128u + (uint32_t)((c ^ (row & 7)) << 4);
}

__device__ __forceinline__ void split2(float x, float y, uint32_t& ph, uint32_t& pl) {
    uint32_t h;
    asm("cvt.rn.bf16x2.f32 %0, %1, %2;" : "=r"(h) : "f"(y), "f"(x));
    float hx = __uint_as_float(h << 16);
    float hy = __uint_as_float(h & 0xffff0000u);
    ph = h;
    asm("cvt.rn.bf16x2.f32 %0, %1, %2;" : "=r"(pl) : "f"(y - hy), "f"(x - hx));
}
__device__ __forceinline__ void split1(float x, __nv_bfloat16& h, __nv_bfloat16& l) {
    h = __float2bfloat16(x);
    l = __float2bfloat16(x - __bfloat162float(h));
}

// one k32 stage, warp tile 64m x 16n (4 m-frags x 2 n-frags).
// A at slot+0 (hi chunks 0-3, lo 4-7), B at slot+16384 (same layout, 64 rows).
__device__ __forceinline__ void cstage(uint32_t slot, float acc[4][2][4],
                                       int mbase, int nbase, int lane) {
    #pragma unroll
    for (int h = 0; h < 2; h++) {
        uint32_t bhf[2][2], blf[2][2];
        {
            int brow = nbase + (lane & 7) + ((lane >> 4) << 3);
            int bch = h * 2 + ((lane >> 3) & 1);
            uint32_t r0, r1, r2, r3;
            ldsm4(r0, r1, r2, r3, slot + 16384u + swz(brow, bch));
            bhf[0][0] = r0; bhf[0][1] = r1; bhf[1][0] = r2; bhf[1][1] = r3;
            ldsm4(r0, r1, r2, r3, slot + 16384u + swz(brow, bch + 4));
            blf[0][0] = r0; blf[0][1] = r1; blf[1][0] = r2; blf[1][1] = r3;
        }
        #pragma unroll
        for (int i = 0; i < 4; i++) {
            int arow = mbase + i * 16 + (lane & 15);
            int ach = h * 2 + (lane >> 4);
            uint32_t ah[4], al[4];
            ldsm4(ah[0], ah[1], ah[2], ah[3], slot + swz(arow, ach));
            ldsm4(al[0], al[1], al[2], al[3], slot + swz(arow, ach + 4));
            #pragma unroll
            for (int j = 0; j < 2; j++) {
                MMA(acc[i][j], ah, bhf[j]);
                MMA(acc[i][j], ah, blf[j]);
                MMA(acc[i][j], al, bhf[j]);
            }
        }
    }
}

// ---------------------------------------------------------------------------
// Kernel 0a/0b: input splits (unchanged).
// ---------------------------------------------------------------------------
__global__ __launch_bounds__(256) void split_hs(const float* __restrict__ hs) {
    int i = (blockIdx.x * 256 + threadIdx.x) * 4;
    float4 v = *(const float4*)&hs[i];
    uint32_t ph0, pl0, ph1, pl1;
    split2(v.x, v.y, ph0, pl0);
    split2(v.z, v.w, ph1, pl1);
    *(uint2*)&s_hs_h[i] = make_uint2(ph0, ph1);
    *(uint2*)&s_hs_l[i] = make_uint2(pl0, pl1);
}

__global__ __launch_bounds__(256) void split_transpose(const float* __restrict__ in,
                                                       __nv_bfloat16* __restrict__ oh,
                                                       __nv_bfloat16* __restrict__ ol,
                                                       int K, int N) {
    __shared__ float t[32][33];
    int nb = blockIdx.x * 32, kb = blockIdx.y * 32;
    int tx = threadIdx.x & 31, ty = threadIdx.x >> 5;
    #pragma unroll
    for (int i = 0; i < 4; i++) {
        int r = ty + i * 8;
        t[r][tx] = in[(size_t)(kb + r) * N + nb + tx];
    }
    __syncthreads();
    #pragma unroll
    for (int i = 0; i < 4; i++) {
        int r = ty + i * 8;
        float v = t[tx][r];
        __nv_bfloat16 h, l; split1(v, h, l);
        size_t o = (size_t)(nb + r) * K + kb + tx;
        oh[o] = h; ol[o] = l;
    }
}

// ---------------------------------------------------------------------------
// Kernel 1: QKV projection. 128m x 64n, warp 64x16, k32 x 32 stages, 2 slots.
// ---------------------------------------------------------------------------
__global__ __launch_bounds__(256, 3) void qkv_gemm(const float* __restrict__ bias) {
    extern __shared__ __align__(16) char dynsmem[];
    const uint32_t smb = s2u(dynsmem);
    const int K = 1024;
    int tid = threadIdx.x, lane = tid & 31, wid = tid >> 5;
    int row0 = blockIdx.y * 128, col0 = blockIdx.x * 64;
    int mbase = (wid & 1) * 64, nbase = (wid >> 1) * 16;
    int srow = tid >> 1, sh = tid & 1;          // A loader
    int brow = tid >> 2, bq = tid & 3;          // B loader
    const __nv_bfloat16* gAh = s_hs_h + (size_t)(row0 + srow) * K + sh * 16;
    const __nv_bfloat16* gAl = s_hs_l + (size_t)(row0 + srow) * K + sh * 16;
    const __nv_bfloat16* gBh = s_wa_h + (size_t)(col0 + brow) * K + bq * 8;
    const __nv_bfloat16* gBl = s_wa_l + (size_t)(col0 + brow) * K + bq * 8;
    uint32_t dA0 = swz(srow, sh * 2),     dA1 = swz(srow, sh * 2 + 1);
    uint32_t dL0 = swz(srow, sh * 2 + 4), dL1 = swz(srow, sh * 2 + 5);
    uint32_t dB0 = 16384u + swz(brow, bq), dB1 = 16384u + swz(brow, bq + 4);

    float acc[4][2][4] = {};
    const int T = K / 32;   // 32

    #define QISSUE(t) do { uint32_t sb = smb + ((t) & 1) * SLOT_G; \
        cpa16(sb + dA0, gAh + (t) * 32);  cpa16(sb + dA1, gAh + (t) * 32 + 8); \
        cpa16(sb + dL0, gAl + (t) * 32);  cpa16(sb + dL1, gAl + (t) * 32 + 8); \
        cpa16(sb + dB0, gBh + (t) * 32);  cpa16(sb + dB1, gBl + (t) * 32); } while (0)

    QISSUE(0); CP_COMMIT();
    for (int t = 0; t < T; t++) {
        CP_WAIT0();
        __syncthreads();
        if (t + 1 < T) QISSUE(t + 1);
        CP_COMMIT();
        cstage(smb + (t & 1) * SLOT_G, acc, mbase, nbase, lane);
    }
    #undef QISSUE

    #pragma unroll
    for (int i = 0; i < 4; i++) {
        #pragma unroll
        for (int j = 0; j < 2; j++) {
            int rr = row0 + mbase + i * 16 + (lane >> 2);
            int cc = col0 + nbase + j * 8 + (lane & 3) * 2;
            #pragma unroll
            for (int half = 0; half < 2; half++) {
                int r = rr + half * 8;
                int b = r >> 11, s = r & 2047;
                float v0 = acc[i][j][half * 2 + 0] + bias[cc];
                float v1 = acc[i][j][half * 2 + 1] + bias[cc + 1];
                uint32_t ph, pl; split2(v0, v1, ph, pl);
                int which = cc >> 10;
                int dcol = cc & 1023;
                int h = dcol >> 6, hd = dcol & 63;
                int bh = b * Hn + h;
                if (which == 0) {
                    size_t idx = ((size_t)bh * Sn + s) * HDn + hd;
                    *(uint32_t*)&g_q_h[idx] = ph; *(uint32_t*)&g_q_l[idx] = pl;
                } else if (which == 1) {
                    size_t idx = ((size_t)bh * Sn + s) * HDn + hd;
                    *(uint32_t*)&g_k_h[idx] = ph; *(uint32_t*)&g_k_l[idx] = pl;
                } else {
                    size_t i0 = ((size_t)bh * HDn + hd) * Sn + s;
                    size_t i1 = ((size_t)bh * HDn + hd + 1) * Sn + s;
                    ((uint16_t*)g_v_h)[i0] = (uint16_t)(ph & 0xffff);
                    ((uint16_t*)g_v_h)[i1] = (uint16_t)(ph >> 16);
                    ((uint16_t*)g_v_l)[i0] = (uint16_t)(pl & 0xffff);
                    ((uint16_t*)g_v_l)[i1] = (uint16_t)(pl >> 16);
                }
            }
        }
    }
}

// ---------------------------------------------------------------------------
// Kernel 2: raw scores, lower-tri 128x128 tiles, K=64 single-shot (unchanged).
// ---------------------------------------------------------------------------
__global__ __launch_bounds__(256, 2) void scores_kernel(const float* __restrict__ mask,
                                                        float* __restrict__ Wout) {
    extern __shared__ __align__(16) char dynsmem[];
    const uint32_t smb = s2u(dynsmem);
    int idx = blockIdx.x;
    int qb = (int)((sqrtf(8.0f * idx + 1.0f) - 1.0f) * 0.5f);
    while ((qb + 1) * (qb + 2) / 2 <= idx) qb++;
    while (qb * (qb + 1) / 2 > idx) qb--;
    int kb = idx - qb * (qb + 1) / 2;
    int bh = blockIdx.y;
    int bb = bh >> 4;
    int tid = threadIdx.x, lane = tid & 31, wid = tid >> 5;
    int row0 = qb * 128, col0 = kb * 128;
    int mbase = (wid & 1) * 64, nbase = (wid >> 1) * 32;
    int srow = tid >> 1, sh = tid & 1;
    const __nv_bfloat16* gAh = g_q_h + ((size_t)bh * Sn + row0 + srow) * HDn + sh * 32;
    const __nv_bfloat16* gAl = g_q_l + ((size_t)bh * Sn + row0 + srow) * HDn + sh * 32;
    const __nv_bfloat16* gBh = g_k_h + ((size_t)bh * Sn + col0 + srow) * HDn + sh * 32;
    const __nv_bfloat16* gBl = g_k_l + ((size_t)bh * Sn + col0 + srow) * HDn + sh * 32;

    #pragma unroll
    for (int i = 0; i < 4; i++) {
        uint32_t d = swz(srow, sh * 4 + i);
        cpa16(smb + d,          gAh + i * 8);
        cpa16(smb + 16384 + d,  gAl + i * 8);
        cpa16(smb + 32768 + d,  gBh + i * 8);
        cpa16(smb + 49152 + d,  gBl + i * 8);
    }
    CP_COMMIT();
    CP_WAIT0();
    __syncthreads();

    float acc[4][4][4] = {};
    #pragma unroll
    for (int h = 0; h < 4; h++) {
        uint32_t bhf[4][2], blf[4][2];
        #pragma unroll
        for (int jg = 0; jg < 2; jg++) {
            int brow = nbase + jg * 16 + (lane & 7) + ((lane >> 4) << 3);
            int bch = h * 2 + ((lane >> 3) & 1);
            uint32_t r0, r1, r2, r3;
            ldsm4(r0, r1, r2, r3, smb + 32768u + swz(brow, bch));
            bhf[jg * 2][0] = r0; bhf[jg * 2][1] = r1;
            bhf[jg * 2 + 1][0] = r2; bhf[jg * 2 + 1][1] = r3;
            ldsm4(r0, r1, r2, r3, smb + 49152u + swz(brow, bch));
            blf[jg * 2][0] = r0; blf[jg * 2][1] = r1;
            blf[jg * 2 + 1][0] = r2; blf[jg * 2 + 1][1] = r3;
        }
        #pragma unroll
        for (int i = 0; i < 4; i++) {
            int arow = mbase + i * 16 + (lane & 15);
            int ach = h * 2 + (lane >> 4);
            uint32_t ah[4], al[4];
            ldsm4(ah[0], ah[1], ah[2], ah[3], smb + swz(arow, ach));
            ldsm4(al[0], al[1], al[2], al[3], smb + 16384u + swz(arow, ach));
            #pragma unroll
            for (int j = 0; j < 4; j++) {
                MMA(acc[i][j], ah, bhf[j]);
                MMA(acc[i][j], ah, blf[j]);
                MMA(acc[i][j], al, bhf[j]);
            }
        }
    }

    const float scale = 0.125f;
    #pragma unroll
    for (int i = 0; i < 4; i++) {
        #pragma unroll
        for (int j = 0; j < 4; j++) {
            int rr = row0 + mbase + i * 16 + (lane >> 2);
            int cc = col0 + nbase + j * 8 + (lane & 3) * 2;
            #pragma unroll
            for (int half = 0; half < 2; half++) {
                int r = rr + half * 8;
                float* orow = Wout + ((size_t)bh * Sn + r) * Sn;
                orow[cc]     = acc[i][j][half * 2 + 0] * scale + mask[bb * Sn + cc];
                orow[cc + 1] = acc[i][j][half * 2 + 1] * scale + mask[bb * Sn + cc + 1];
            }
        }
    }
}

// ---------------------------------------------------------------------------
// Kernel 3: row softmax (unchanged).
// ---------------------------------------------------------------------------
__global__ __launch_bounds__(256) void softmax_kernel(float* __restrict__ Wm) {
    __shared__ float buf[Sn];
    __shared__ float red[8];
    int row = blockIdx.x;
    int q = row & (Sn - 1);
    int len = q + 1;
    int blockend = ((q >> 7) + 1) << 7;
    float* wrow = Wm + (size_t)row * Sn;
    size_t wb = (size_t)row * Sn;
    int tid = threadIdx.x;
    int lane = tid & 31, warp = tid >> 5;

    float mx = -1e30f;
    for (int c = tid * 4; c < blockend; c += 1024) {
        float4 v = *(const float4*)&wrow[c];
        *(float4*)&buf[c] = v;
        if (c + 3 < len) {
            mx = fmaxf(mx, fmaxf(fmaxf(v.x, v.y), fmaxf(v.z, v.w)));
        } else {
            if (c     < len) mx = fmaxf(mx, v.x);
            if (c + 1 < len) mx = fmaxf(mx, v.y);
            if (c + 2 < len) mx = fmaxf(mx, v.z);
            if (c + 3 < len) mx = fmaxf(mx, v.w);
        }
    }
    #pragma unroll
    for (int o = 16; o > 0; o >>= 1) mx = fmaxf(mx, __shfl_xor_sync(0xffffffffu, mx, o));
    if (lane == 0) red[warp] = mx;
    __syncthreads();
    if (tid < 32) {
        float t = (tid < 8) ? red[tid] : -1e30f;
        #pragma unroll
        for (int o = 4; o > 0; o >>= 1) t = fmaxf(t, __shfl_xor_sync(0xffffffffu, t, o));
        if (tid == 0) red[0] = t;
    }
    __syncthreads();
    mx = red[0];
    __syncthreads();

    float sum = 0.0f;
    for (int c = tid * 4; c < blockend; c += 1024) {
        float4 v = *(const float4*)&buf[c];
        float e0 = (c     < len) ? __expf(v.x - mx) : 0.0f;
        float e1 = (c + 1 < len) ? __expf(v.y - mx) : 0.0f;
        float e2 = (c + 2 < len) ? __expf(v.z - mx) : 0.0f;
        float e3 = (c + 3 < len) ? __expf(v.w - mx) : 0.0f;
        sum += (e0 + e1) + (e2 + e3);
        *(float4*)&buf[c] = make_float4(e0, e1, e2, e3);
    }
    #pragma unroll
    for (int o = 16; o > 0; o >>= 1) sum += __shfl_xor_sync(0xffffffffu, sum, o);
    if (lane == 0) red[warp] = sum;
    __syncthreads();
    if (tid < 32) {
        float t = (tid < 8) ? red[tid] : 0.0f;
        #pragma unroll
        for (int o = 4; o > 0; o >>= 1) t += __shfl_xor_sync(0xffffffffu, t, o);
        if (tid == 0) red[0] = t;
    }
    __syncthreads();
    float inv = 1.0f / red[0];

    for (int c = tid * 4; c < blockend; c += 1024) {
        float4 v = *(const float4*)&buf[c];
        v.x *= inv; v.y *= inv; v.z *= inv; v.w *= inv;
        *(float4*)&wrow[c] = v;
        uint32_t ph0, pl0, ph1, pl1;
        split2(v.x, v.y, ph0, pl0);
        split2(v.z, v.w, ph1, pl1);
        *(uint2*)&g_w_h[wb + c] = make_uint2(ph0, ph1);
        *(uint2*)&g_w_l[wb + c] = make_uint2(pl0, pl1);
    }
    for (int c = blockend + tid * 4; c < Sn; c += 1024)
        *(float4*)&wrow[c] = make_float4(0.f, 0.f, 0.f, 0.f);
}

// ---------------------------------------------------------------------------
// Kernel 4: attn_heads = weights @ V. 128m x 64n, warp 64x16, k32, 2 slots.
// ---------------------------------------------------------------------------
__global__ __launch_bounds__(256, 3) void av_kernel() {
    extern __shared__ __align__(16) char dynsmem[];
    const uint32_t smb = s2u(dynsmem);
    int qb = gridDim.x - 1 - blockIdx.x;   // longest first
    int bh = blockIdx.y;
    int tid = threadIdx.x, lane = tid & 31, wid = tid >> 5;
    int row0 = qb * 128;
    int mbase = (wid & 1) * 64, nbase = (wid >> 1) * 16;
    int srow = tid >> 1, sh = tid & 1;
    int brow = tid >> 2, bq = tid & 3;
    const __nv_bfloat16* gAh = g_w_h + (size_t)bh * Sn * Sn + (size_t)(row0 + srow) * Sn + sh * 16;
    const __nv_bfloat16* gAl = g_w_l + (size_t)bh * Sn * Sn + (size_t)(row0 + srow) * Sn + sh * 16;
    const __nv_bfloat16* gBh = g_v_h + ((size_t)bh * HDn + brow) * Sn + bq * 8;
    const __nv_bfloat16* gBl = g_v_l + ((size_t)bh * HDn + brow) * Sn + bq * 8;
    uint32_t dA0 = swz(srow, sh * 2),     dA1 = swz(srow, sh * 2 + 1);
    uint32_t dL0 = swz(srow, sh * 2 + 4), dL1 = swz(srow, sh * 2 + 5);
    uint32_t dB0 = 16384u + swz(brow, bq), dB1 = 16384u + swz(brow, bq + 4);

    float acc[4][2][4] = {};
    const int T = (qb + 1) * 4;

    #define AISSUE(t) do { uint32_t sb = smb + ((t) & 1) * SLOT_G; \
        cpa16(sb + dA0, gAh + (t) * 32);  cpa16(sb + dA1, gAh + (t) * 32 + 8); \
        cpa16(sb + dL0, gAl + (t) * 32);  cpa16(sb + dL1, gAl + (t) * 32 + 8); \
        cpa16(sb + dB0, gBh + (t) * 32);  cpa16(sb + dB1, gBl + (t) * 32); } while (0)

    AISSUE(0); CP_COMMIT();
    for (int t = 0; t < T; t++) {
        CP_WAIT0();
        __syncthreads();
        if (t + 1 < T) AISSUE(t + 1);
        CP_COMMIT();
        cstage(smb + (t & 1) * SLOT_G, acc, mbase, nbase, lane);
    }
    #undef AISSUE

    #pragma unroll
    for (int i = 0; i < 4; i++) {
        #pragma unroll
        for (int j = 0; j < 2; j++) {
            int rr = row0 + mbase + i * 16 + (lane >> 2);
            int cc = nbase + j * 8 + (lane & 3) * 2;
            #pragma unroll
            for (int half = 0; half < 2; half++) {
                int r = rr + half * 8;
                uint32_t ph, pl;
                split2(acc[i][j][half * 2 + 0], acc[i][j][half * 2 + 1], ph, pl);
                size_t idx = ((size_t)bh * Sn + r) * HDn + cc;
                *(uint32_t*)&g_att_h[idx] = ph;
                *(uint32_t*)&g_att_l[idx] = pl;
            }
        }
    }
}

// ---------------------------------------------------------------------------
// Kernel 5: output projection. 128m x 64n, warp 64x16, k32, 2 slots.
// ---------------------------------------------------------------------------
__global__ __launch_bounds__(256, 3) void proj_gemm(const float* __restrict__ bias,
                                                    float* __restrict__ out) {
    extern __shared__ __align__(16) char dynsmem[];
    const uint32_t smb = s2u(dynsmem);
    const int K = 1024, N = 1024;
    int tid = threadIdx.x, lane = tid & 31, wid = tid >> 5;
    int row0 = blockIdx.y * 128, col0 = blockIdx.x * 64;
    int mbase = (wid & 1) * 64, nbase = (wid >> 1) * 16;
    int srow = tid >> 1, sh = tid & 1;
    int brow = tid >> 2, bq = tid & 3;
    int arow = row0 + srow;
    int ab = arow >> 11, as = arow & 2047;
    size_t abase = (((size_t)ab * Hn) * Sn + as) * HDn;  // + head*Sn*HDn + hd
    const __nv_bfloat16* gBh = s_wp_h + (size_t)(col0 + brow) * K + bq * 8;
    const __nv_bfloat16* gBl = s_wp_l + (size_t)(col0 + brow) * K + bq * 8;
    uint32_t dA0 = swz(srow, sh * 2),     dA1 = swz(srow, sh * 2 + 1);
    uint32_t dL0 = swz(srow, sh * 2 + 4), dL1 = swz(srow, sh * 2 + 5);
    uint32_t dB0 = 16384u + swz(brow, bq), dB1 = 16384u + swz(brow, bq + 4);

    float acc[4][2][4] = {};
    const int T = K / 32;   // 32; stage t covers head t>>1, hd half (t&1)*32

    #define PISSUE(t) do { uint32_t sb = smb + ((t) & 1) * SLOT_G; \
        size_t so = abase + (size_t)((t) >> 1) * Sn * HDn + ((t) & 1) * 32 + sh * 16; \
        cpa16(sb + dA0, g_att_h + so);  cpa16(sb + dA1, g_att_h + so + 8); \
        cpa16(sb + dL0, g_att_l + so);  cpa16(sb + dL1, g_att_l + so + 8); \
        cpa16(sb + dB0, gBh + (t) * 32); cpa16(sb + dB1, gBl + (t) * 32); } while (0)

    PISSUE(0); CP_COMMIT();
    for (int t = 0; t < T; t++) {
        CP_WAIT0();
        __syncthreads();
        if (t + 1 < T) PISSUE(t + 1);
        CP_COMMIT();
        cstage(smb + (t & 1) * SLOT_G, acc, mbase, nbase, lane);
    }
    #undef PISSUE

    #pragma unroll
    for (int i = 0; i < 4; i++) {
        #pragma unroll
        for (int j = 0; j < 2; j++) {
            int rr = row0 + mbase + i * 16 + (lane >> 2);
            int cc = col0 + nbase + j * 8 + (lane & 3) * 2;
            #pragma unroll
            for (int half = 0; half < 2; half++) {
                int r = rr + half * 8;
                out[(size_t)r * N + cc]     = acc[i][j][half * 2 + 0] + bias[cc];
                out[(size_t)r * N + cc + 1] = acc[i][j][half * 2 + 1] + bias[cc + 1];
            }
        }
    }
}

// ---------------------------------------------------------------------------
extern "C" void kernel_launch(void* const* d_in, const int* in_sizes, int n_in,
                              void* d_out, int out_size) {
    (void)in_sizes; (void)n_in; (void)out_size;
    const float* hs     = (const float*)d_in[0];
    const float* mask   = (const float*)d_in[1];
    const float* w_attn = (const float*)d_in[2];
    const float* b_attn = (const float*)d_in[3];
    const float* w_proj = (const float*)d_in[4];
    const float* b_proj = (const float*)d_in[5];

    float* attn_out = (float*)d_out;                          // [B,S,D]
    float* weights  = (float*)d_out + (size_t)Bn * Sn * Dn;   // [B,H,S,S]

    cudaFuncSetAttribute(qkv_gemm,      cudaFuncAttributeMaxDynamicSharedMemorySize, SMEM_G);
    cudaFuncSetAttribute(scores_kernel, cudaFuncAttributeMaxDynamicSharedMemorySize, SMEM_SC);
    cudaFuncSetAttribute(av_kernel,     cudaFuncAttributeMaxDynamicSharedMemorySize, SMEM_G);
    cudaFuncSetAttribute(proj_gemm,     cudaFuncAttributeMaxDynamicSharedMemorySize, SMEM_G);

    __nv_bfloat16 *wa_h, *wa_l, *wp_h, *wp_l;
    cudaGetSymbolAddress((void**)&wa_h, s_wa_h);
    cudaGetSymbolAddress((void**)&wa_l, s_wa_l);
    cudaGetSymbolAddress((void**)&wp_h, s_wp_h);
    cudaGetSymbolAddress((void**)&wp_l, s_wp_l);

    split_hs<<<BSn * Dn / 1024, 256>>>(hs);
    split_transpose<<<dim3(N3D / 32, Dn / 32), 256>>>(w_attn, wa_h, wa_l, Dn, N3D);
    split_transpose<<<dim3(Dn / 32, Dn / 32), 256>>>(w_proj, wp_h, wp_l, Dn, Dn);
    qkv_gemm<<<dim3(N3D / 64, BSn / 128), 256, SMEM_G>>>(b_attn);
    scores_kernel<<<dim3(136, Bn * Hn), 256, SMEM_SC>>>(mask, weights);
    softmax_kernel<<<dim3(Bn * Hn * Sn), 256>>>(weights);
    av_kernel<<<dim3(Sn / 128, Bn * Hn), 256, SMEM_G>>>();
    proj_gemm<<<dim3(Dn / 64, BSn / 128), 256, SMEM_G>>>(b_proj, attn_out);
}